// round 12
// baseline (speedup 1.0000x reference)
#include <cuda_runtime.h>

// x: (B=64, W=512, H=48, M=64) fp32, row-major.
// out[b, ((iw*6 + ih)*64 + m)] = max over w in [iw*32, iw*32+32), h in [ih*8, ih*8+8) of x[b,w,h,m]
// Exact bins: 512/16 = 32, 48/6 = 8 (round(k*p) boundaries are integral).
//
// FINAL, converged (benched 4x: 61.89 / 62.18 / 61.98 / 62.18 us):
//   - one CTA per (b,iw,ih) output tile: 6144 CTAs x 256 threads
//   - 32 regs -> 8 CTAs/SM = 100% register file, occ ~96%
//   - 16 fully unrolled independent LDG.128 per thread (MLP 16); each warp
//     reads 512 contiguous bytes per unroll step (perfect coalescing)
//   - compulsory-traffic bound: 402.7 MB read once at 6.7-6.8 TB/s
//     (~84% of 8 TB/s spec = the achieved HBM ceiling; the LTS cap is
//     path-independent, so TMA/cp.async could not exceed it)
// Rejected by measurement: locality restructure at lower occupancy (-4%),
// __ldcs / grid order / batch split (neutral), barrier-count tweaks (neutral),
// persistent single-wave grid (-17%: per-tile barriers drain MLP; hardware
// CTA replacement is free).

constexpr int B_  = 64;
constexpr int W_  = 512;
constexpr int H_  = 48;
constexpr int M_  = 64;
constexpr int PW  = 16;
constexpr int PH  = 6;
constexpr int WB  = W_ / PW;  // 32
constexpr int HB  = H_ / PH;  // 8

__device__ __forceinline__ float4 max4(float4 a, float4 b) {
    float4 r;
    r.x = fmaxf(a.x, b.x);
    r.y = fmaxf(a.y, b.y);
    r.z = fmaxf(a.z, b.z);
    r.w = fmaxf(a.w, b.w);
    return r;
}

__global__ __launch_bounds__(256, 8)
void dap_pool_kernel(const float* __restrict__ x, float* __restrict__ out) {
    const int iw = blockIdx.x;   // 0..15
    const int ih = blockIdx.y;   // 0..5
    const int b  = blockIdx.z;   // 0..63

    const int tid = threadIdx.x;       // 0..255
    const int m4  = tid & 15;          // float4 lane over M (16 * 4 = 64)
    const int sub = tid >> 4;          // 0..15 window subsets

    // Base pointer for this (b, iw, ih) tile, as float4 over M.
    const float4* __restrict__ xb =
        reinterpret_cast<const float4*>(x) +
        ((size_t)b * W_ * H_ + (size_t)(iw * WB) * H_ + (size_t)(ih * HB)) * (M_ / 4);

    // Window has WB*HB = 256 cells; each thread handles 16 cells: c = sub + 16*i.
    float4 acc = make_float4(-INFINITY, -INFINITY, -INFINITY, -INFINITY);
#pragma unroll
    for (int i = 0; i < 16; i++) {
        const int c = sub + (i << 4);      // 0..255
        const int wl = c >> 3;             // 0..31  (local w)
        const int hl = c & 7;              // 0..7   (local h)
        const float4 v = __ldg(&xb[((size_t)wl * H_ + hl) * (M_ / 4) + m4]);
        acc = max4(acc, v);
    }

    // Tree reduce across the 16 subsets in shared memory.
    __shared__ float4 smem[256];
    smem[tid] = acc;
    __syncthreads();
#pragma unroll
    for (int st = 128; st >= 16; st >>= 1) {
        if (tid < st) smem[tid] = max4(smem[tid], smem[tid + st]);
        __syncthreads();
    }

    if (tid < 16) {
        // out[b, (iw*PH + ih)*M + m4*4 .. +3]
        float4* o4 = reinterpret_cast<float4*>(out);
        o4[(size_t)b * (PW * PH * (M_ / 4)) + (size_t)(iw * PH + ih) * (M_ / 4) + m4] = smem[tid];
    }
}

extern "C" void kernel_launch(void* const* d_in, const int* in_sizes, int n_in,
                              void* d_out, int out_size) {
    const float* x = (const float*)d_in[0];
    float* out = (float*)d_out;
    dim3 grid(PW, PH, B_);
    dap_pool_kernel<<<grid, 256>>>(x, out);
}

// round 13
// speedup vs baseline: 1.0057x; 1.0057x over previous
#include <cuda_runtime.h>

// x: (B=64, W=512, H=48, M=64) fp32, row-major.
// out[b, ((iw*6 + ih)*64 + m)] = max over w in [iw*32, iw*32+32), h in [ih*8, ih*8+8) of x[b,w,h,m]
// Exact bins: 512/16 = 32, 48/6 = 8 (round(k*p) boundaries are integral).
//
// FINAL, converged (benched 5x: 61.89 / 62.18 / 61.98 / 62.18 / 62.21 us;
// DRAM 82.5-85.6% = noise band of a fixed-traffic kernel):
//   - one CTA per (b,iw,ih) output tile: 6144 CTAs x 256 threads
//   - 32 regs -> 8 CTAs/SM: 100% register file AND 64 warps/SM (both HW maxima)
//   - 16 fully unrolled independent LDG.128 per thread (MLP 16); each warp
//     reads 512 contiguous bytes per unroll step (perfect coalescing)
//   - compulsory-traffic bound: 402.7 MB read once at 6.6-6.8 TB/s, the
//     path-independent achieved HBM/LTS ceiling (TMA/cp.async cannot exceed it)
// Rejected by measurement: locality restructure at lower occupancy (-4%),
// __ldcs / grid order / batch split (neutral), barrier-count tweaks (neutral),
// persistent single-wave grid (-17%: per-tile barriers drain MLP; hardware
// CTA replacement is free).

constexpr int B_  = 64;
constexpr int W_  = 512;
constexpr int H_  = 48;
constexpr int M_  = 64;
constexpr int PW  = 16;
constexpr int PH  = 6;
constexpr int WB  = W_ / PW;  // 32
constexpr int HB  = H_ / PH;  // 8

__device__ __forceinline__ float4 max4(float4 a, float4 b) {
    float4 r;
    r.x = fmaxf(a.x, b.x);
    r.y = fmaxf(a.y, b.y);
    r.z = fmaxf(a.z, b.z);
    r.w = fmaxf(a.w, b.w);
    return r;
}

__global__ __launch_bounds__(256, 8)
void dap_pool_kernel(const float* __restrict__ x, float* __restrict__ out) {
    const int iw = blockIdx.x;   // 0..15
    const int ih = blockIdx.y;   // 0..5
    const int b  = blockIdx.z;   // 0..63

    const int tid = threadIdx.x;       // 0..255
    const int m4  = tid & 15;          // float4 lane over M (16 * 4 = 64)
    const int sub = tid >> 4;          // 0..15 window subsets

    // Base pointer for this (b, iw, ih) tile, as float4 over M.
    const float4* __restrict__ xb =
        reinterpret_cast<const float4*>(x) +
        ((size_t)b * W_ * H_ + (size_t)(iw * WB) * H_ + (size_t)(ih * HB)) * (M_ / 4);

    // Window has WB*HB = 256 cells; each thread handles 16 cells: c = sub + 16*i.
    float4 acc = make_float4(-INFINITY, -INFINITY, -INFINITY, -INFINITY);
#pragma unroll
    for (int i = 0; i < 16; i++) {
        const int c = sub + (i << 4);      // 0..255
        const int wl = c >> 3;             // 0..31  (local w)
        const int hl = c & 7;              // 0..7   (local h)
        const float4 v = __ldg(&xb[((size_t)wl * H_ + hl) * (M_ / 4) + m4]);
        acc = max4(acc, v);
    }

    // Tree reduce across the 16 subsets in shared memory.
    __shared__ float4 smem[256];
    smem[tid] = acc;
    __syncthreads();
#pragma unroll
    for (int st = 128; st >= 16; st >>= 1) {
        if (tid < st) smem[tid] = max4(smem[tid], smem[tid + st]);
        __syncthreads();
    }

    if (tid < 16) {
        // out[b, (iw*PH + ih)*M + m4*4 .. +3]
        float4* o4 = reinterpret_cast<float4*>(out);
        o4[(size_t)b * (PW * PH * (M_ / 4)) + (size_t)(iw * PH + ih) * (M_ / 4) + m4] = smem[tid];
    }
}

extern "C" void kernel_launch(void* const* d_in, const int* in_sizes, int n_in,
                              void* d_out, int out_size) {
    const float* x = (const float*)d_in[0];
    float* out = (float*)d_out;
    dim3 grid(PW, PH, B_);
    dap_pool_kernel<<<grid, 256>>>(x, out);
}